// round 3
// baseline (speedup 1.0000x reference)
#include <cuda_runtime.h>
#include <cstddef>

// PCEN: out = (x / (FLOOR + ema(x))^alpha + delta)^(1/root) - delta^(1/root)
// ema: m_t = s*x_t + (1-s)*m_{t-1}, m_0 = x_0, s = 0.025.
//
// R3: 16 chunks (CHUNK=256, HALO=257 -> decay 1.5e-3, output err ~1.4e-4),
// 2048 warps for ~21% occupancy, and a double-buffered tile pipeline so each
// warp always has a load batch in flight while computing the previous tile.

namespace {
constexpr int   Bn = 64, Tn = 4096, Cn = 128;
constexpr float S_COEF = 0.025f;
constexpr float INV_S  = 40.0f;
constexpr float OMS    = 0.975f;
constexpr float FLOORV = 1e-6f;
constexpr int   NC     = 16;              // chunks along T
constexpr int   CHUNK  = Tn / NC;         // 256
constexpr int   HALO   = 257;             // 256 burn-in updates (multiple of U)
constexpr int   U      = 8;               // rows per tile
constexpr int   THREADS = 128;            // 4 warps/block
constexpr int   NWARPS  = Bn * NC * 2;    // 2048 float2-warps
constexpr int   NBLOCKS = NWARPS * 32 / THREADS;  // 512
constexpr int   STRIDE  = Cn / 2;         // float2 elems per T-row
}

__device__ __forceinline__ float f_lg2(float x) {
    float r; asm("lg2.approx.f32 %0, %1;" : "=f"(r) : "f"(x)); return r;
}
__device__ __forceinline__ float f_ex2(float x) {
    float r; asm("ex2.approx.f32 %0, %1;" : "=f"(r) : "f"(x)); return r;
}
__device__ __forceinline__ float f_sqt(float x) {
    float r; asm("sqrt.approx.f32 %0, %1;" : "=f"(r) : "f"(x)); return r;
}

// Pointwise PCEN. mp = m/S (scaled EMA state). SQ = (1/root == 0.5) fast path.
template <bool SQ>
__device__ __forceinline__ float pcen_pt(float xv, float mp, float na, float d,
                                         float ri, float t3) {
    float mm     = fmaf(S_COEF, mp, FLOORV);       // FLOOR + m (off the chain)
    float inv_t1 = f_ex2(na * f_lg2(mm));          // (FLOOR+m)^(-alpha)
    float y      = fmaf(xv, inv_t1, d);            // x/term1 + delta
    float t2     = SQ ? f_sqt(y) : f_ex2(ri * f_lg2(y));
    return t2 - t3;
}

template <bool SQ>
__device__ __forceinline__ void emit_row(float2 xv, float& mx, float& my,
                                         float2* __restrict__ po,
                                         float2 na, float2 d, float2 ri, float2 t3) {
    mx = fmaf(OMS, mx, xv.x);                      // 4-cyc dependent chain
    my = fmaf(OMS, my, xv.y);
    float2 o;
    o.x = pcen_pt<SQ>(xv.x, mx, na.x, d.x, ri.x, t3.x);
    o.y = pcen_pt<SQ>(xv.y, my, na.y, d.y, ri.y, t3.y);
    __stcs(po, o);                                 // streaming store
}

// Walk nh halo rows then ne emit rows, contiguous from p, tiles of U rows,
// double buffered so next tile's loads overlap this tile's math.
// Requires nh % U == 0.
template <bool SQ>
__device__ __forceinline__ void run_seq(const float2* __restrict__ p,
                                        float2* __restrict__ po,
                                        int nh, int ne, float& mx, float& my,
                                        float2 na, float2 d, float2 ri, float2 t3) {
    int total  = nh + ne;
    int ntiles = total / U;
    int rem    = total - ntiles * U;

    float2 buf[2][U];
    #pragma unroll
    for (int i = 0; i < U; ++i) buf[0][i] = p[i * STRIDE];

    for (int t = 0; t < ntiles; ++t) {
        float2* cur = buf[t & 1];
        float2* nxt = buf[(t + 1) & 1];
        const float2* pn = p + (size_t)(t + 1) * U * STRIDE;
        if (t + 1 < ntiles) {
            #pragma unroll
            for (int i = 0; i < U; ++i) nxt[i] = pn[i * STRIDE];
        } else {
            #pragma unroll
            for (int i = 0; i < U; ++i) if (i < rem) nxt[i] = pn[i * STRIDE];
        }
        if (t * U >= nh) {                          // emit tile (warp-uniform)
            float2* pot = po + (size_t)(t * U - nh) * STRIDE;
            #pragma unroll
            for (int i = 0; i < U; ++i)
                emit_row<SQ>(cur[i], mx, my, pot + i * STRIDE, na, d, ri, t3);
        } else {                                    // halo tile: EMA update only
            #pragma unroll
            for (int i = 0; i < U; ++i) {
                mx = fmaf(OMS, mx, cur[i].x);
                my = fmaf(OMS, my, cur[i].y);
            }
        }
    }
    // epilogue: rem emit rows (rem only nonzero for chunk 0, all-emit)
    float2* cur = buf[ntiles & 1];
    float2* pot = po + (size_t)(ntiles * U - nh) * STRIDE;
    #pragma unroll
    for (int i = 0; i < U; ++i)
        if (i < rem) emit_row<SQ>(cur[i], mx, my, pot + i * STRIDE, na, d, ri, t3);
}

__global__ void __launch_bounds__(THREADS)
pcen_kernel(const float* __restrict__ x,
            const float* __restrict__ alpha,
            const float* __restrict__ delta,
            const float* __restrict__ root,
            float* __restrict__ out) {
    int gtid = blockIdx.x * blockDim.x + threadIdx.x;
    int w    = gtid >> 5;
    int lane = threadIdx.x & 31;

    // warp -> (b, chunk, half); 32 warps per batch; thread -> 2 channels
    int b     = w >> 5;
    int r     = w & 31;
    int chunk = r >> 1;
    int half  = r & 1;
    int c     = half * 64 + lane * 2;

    float2 a2 = *(const float2*)(alpha + c);
    float2 d2 = *(const float2*)(delta + c);
    float2 r2 = *(const float2*)(root  + c);

    float2 na, ri, t3;
    na.x = -fminf(a2.x, 1.0f);
    na.y = -fminf(a2.y, 1.0f);
    ri.x = 1.0f / fmaxf(r2.x, 1.0f);
    ri.y = 1.0f / fmaxf(r2.y, 1.0f);
    bool sq = (ri.x == 0.5f) && (ri.y == 0.5f);
    // term3 via the SAME approx path as term2 so the x->0 limit cancels exactly
    t3.x = sq ? f_sqt(d2.x) : f_ex2(ri.x * f_lg2(d2.x));
    t3.y = sq ? f_sqt(d2.y) : f_ex2(ri.y * f_lg2(d2.y));

    int t0     = chunk * CHUNK;
    int tstart = (chunk == 0) ? 0 : t0 - HALO;

    const float2* px = (const float2*)(x   + ((size_t)b * Tn + tstart) * Cn + c);
    float2*       po = (float2*)      (out + ((size_t)b * Tn + t0)     * Cn + c);

    // m-init row (exact for chunk 0, approx deep inside halo otherwise)
    float2 x0 = px[0];
    float mx = x0.x * INV_S;            // scaled state m' = m/S
    float my = x0.y * INV_S;

    int nh, ne;
    if (chunk == 0) {                   // emit row 0 immediately (m = x_0 exact)
        float2 o;
        o.x = pcen_pt<(true)>(x0.x, mx, na.x, d2.x, ri.x, t3.x);  // placeholder; fixed below
        // NOTE: need SQ-dispatch for row 0 too — do it in the dispatch below.
        nh = 0; ne = CHUNK - 1;
        (void)o;
    } else {
        nh = HALO - 1;  ne = CHUNK;     // nh = 256, multiple of U
    }

    if (sq) {
        if (chunk == 0) {
            float2 o;
            o.x = pcen_pt<true>(x0.x, mx, na.x, d2.x, ri.x, t3.x);
            o.y = pcen_pt<true>(x0.y, my, na.y, d2.y, ri.y, t3.y);
            __stcs(po, o);
            run_seq<true>(px + STRIDE, po + STRIDE, nh, ne, mx, my, na, d2, ri, t3);
        } else {
            run_seq<true>(px + STRIDE, po, nh, ne, mx, my, na, d2, ri, t3);
        }
    } else {
        if (chunk == 0) {
            float2 o;
            o.x = pcen_pt<false>(x0.x, mx, na.x, d2.x, ri.x, t3.x);
            o.y = pcen_pt<false>(x0.y, my, na.y, d2.y, ri.y, t3.y);
            __stcs(po, o);
            run_seq<false>(px + STRIDE, po + STRIDE, nh, ne, mx, my, na, d2, ri, t3);
        } else {
            run_seq<false>(px + STRIDE, po, nh, ne, mx, my, na, d2, ri, t3);
        }
    }
}

extern "C" void kernel_launch(void* const* d_in, const int* in_sizes, int n_in,
                              void* d_out, int out_size) {
    const float* x     = (const float*)d_in[0];
    const float* alpha = (const float*)d_in[1];
    const float* delta = (const float*)d_in[2];
    const float* root  = (const float*)d_in[3];
    float*       out   = (float*)d_out;
    (void)in_sizes; (void)n_in; (void)out_size;

    pcen_kernel<<<NBLOCKS, THREADS>>>(x, alpha, delta, root, out);
}

// round 4
// speedup vs baseline: 1.2479x; 1.2479x over previous
#include <cuda_runtime.h>
#include <cstddef>

// PCEN: out = (x / (FLOOR + ema(x))^alpha + delta)^(1/root) - delta^(1/root)
// ema: m_t = s*x_t + (1-s)*m_{t-1}, m_0 = x_0, s = 0.025.
//
// R4: R2's register-resident phased loop (static fully-unrolled tile buffer,
// NO dynamic buffer indexing -> no spills) combined with R3's concurrency:
// NC=16 chunks (CHUNK=256, HALO=257 -> rel_err ~2e-4), 2048 warps (~21% occ).
// Halo re-reads hit L2; output stores streamed (.cs).

namespace {
constexpr int   Bn = 64, Tn = 4096, Cn = 128;
constexpr float S_COEF = 0.025f;
constexpr float INV_S  = 40.0f;
constexpr float OMS    = 0.975f;
constexpr float FLOORV = 1e-6f;
constexpr int   NC     = 16;              // chunks along T
constexpr int   CHUNK  = Tn / NC;         // 256
constexpr int   HALO   = 257;             // 256 burn-in updates -> decay 1.5e-3
constexpr int   U      = 16;              // rows per tile (MLP)
constexpr int   THREADS = 128;            // 4 warps/block
constexpr int   NWARPS  = Bn * NC * 2;    // 2048 float2-warps
constexpr int   NBLOCKS = NWARPS * 32 / THREADS;  // 512
constexpr int   STRIDE  = Cn / 2;         // float2 elems per T-row
}

__device__ __forceinline__ float f_lg2(float x) {
    float r; asm("lg2.approx.f32 %0, %1;" : "=f"(r) : "f"(x)); return r;
}
__device__ __forceinline__ float f_ex2(float x) {
    float r; asm("ex2.approx.f32 %0, %1;" : "=f"(r) : "f"(x)); return r;
}
__device__ __forceinline__ float f_sqt(float x) {
    float r; asm("sqrt.approx.f32 %0, %1;" : "=f"(r) : "f"(x)); return r;
}

// Pointwise PCEN. mp = m/S (scaled EMA state). SQ = (1/root == 0.5) fast path.
template <bool SQ>
__device__ __forceinline__ float pcen_pt(float xv, float mp, float na, float d,
                                         float ri, float t3) {
    float mm     = fmaf(S_COEF, mp, FLOORV);       // FLOOR + m (off the chain)
    float inv_t1 = f_ex2(na * f_lg2(mm));          // (FLOOR+m)^(-alpha)
    float y      = fmaf(xv, inv_t1, d);            // x/term1 + delta
    float t2     = SQ ? f_sqt(y) : f_ex2(ri * f_lg2(y));
    return t2 - t3;
}

template <bool SQ>
__device__ __forceinline__ void run_seq(const float2* __restrict__ px,
                                        float2* __restrict__ po,
                                        int tstart, int t0, int tend,
                                        float2 na, float2 d, float2 ri, float2 t3) {
    float2 x0 = px[0];
    float mx = x0.x * INV_S;            // scaled state m' = m/S; m_init = x_init
    float my = x0.y * INV_S;
    const float2* p = px + STRIDE;

    if (tstart == t0) {                 // chunk 0 emits row 0 (m = x_0, exact)
        float2 o;
        o.x = pcen_pt<SQ>(x0.x, mx, na.x, d.x, ri.x, t3.x);
        o.y = pcen_pt<SQ>(x0.y, my, na.y, d.y, ri.y, t3.y);
        __stcs(po, o);
        po += STRIDE;
    }

    // ---- halo burn-in: EMA update only, batched loads ----
    int nh = t0 - (tstart + 1);         // 256 for chunks > 0, -1 for chunk 0
    int hb = nh / U;                    // 16 full tiles (nh divisible by U)
    for (int g = 0; g < hb; ++g) {
        float2 xs[U];
        #pragma unroll
        for (int i = 0; i < U; ++i) xs[i] = p[i * STRIDE];
        #pragma unroll
        for (int i = 0; i < U; ++i) {
            mx = fmaf(OMS, mx, xs[i].x);
            my = fmaf(OMS, my, xs[i].y);
        }
        p += U * STRIDE;
    }
    int hr = nh - hb * U;               // 0 for chunks > 0
    for (int i = 0; i < hr; ++i) {
        float2 xv = p[i * STRIDE];
        mx = fmaf(OMS, mx, xv.x);
        my = fmaf(OMS, my, xv.y);
    }
    if (hr > 0) p += hr * STRIDE;

    // ---- emit region ----
    int ne = (tstart == t0) ? (tend - t0 - 1) : (tend - t0);
    int mt = ne / U;
    int rem = ne - mt * U;

    for (int it = 0; it < mt; ++it) {
        float2 xs[U], os[U];
        #pragma unroll
        for (int i = 0; i < U; ++i) xs[i] = p[i * STRIDE];   // batched LDG.64 x16
        #pragma unroll
        for (int i = 0; i < U; ++i) {
            mx = fmaf(OMS, mx, xs[i].x);                     // 4-cyc chain
            my = fmaf(OMS, my, xs[i].y);
            os[i].x = pcen_pt<SQ>(xs[i].x, mx, na.x, d.x, ri.x, t3.x);
            os[i].y = pcen_pt<SQ>(xs[i].y, my, na.y, d.y, ri.y, t3.y);
        }
        #pragma unroll
        for (int i = 0; i < U; ++i) __stcs(po + i * STRIDE, os[i]);
        p  += U * STRIDE;
        po += U * STRIDE;
    }
    for (int i = 0; i < rem; ++i) {
        float2 xv = p[i * STRIDE];
        mx = fmaf(OMS, mx, xv.x);
        my = fmaf(OMS, my, xv.y);
        float2 o;
        o.x = pcen_pt<SQ>(xv.x, mx, na.x, d.x, ri.x, t3.x);
        o.y = pcen_pt<SQ>(xv.y, my, na.y, d.y, ri.y, t3.y);
        __stcs(po + i * STRIDE, o);
    }
}

__global__ void __launch_bounds__(THREADS)
pcen_kernel(const float* __restrict__ x,
            const float* __restrict__ alpha,
            const float* __restrict__ delta,
            const float* __restrict__ root,
            float* __restrict__ out) {
    int gtid = blockIdx.x * blockDim.x + threadIdx.x;
    int w    = gtid >> 5;
    int lane = threadIdx.x & 31;

    // warp -> (b, chunk, half); 32 warps per batch; thread -> 2 channels
    int b     = w >> 5;
    int r     = w & 31;
    int chunk = r >> 1;
    int half  = r & 1;
    int c     = half * 64 + lane * 2;

    // per-channel constants (x2)
    float2 a2 = *(const float2*)(alpha + c);
    float2 d2 = *(const float2*)(delta + c);
    float2 r2 = *(const float2*)(root  + c);

    float2 na, ri, t3;
    na.x = -fminf(a2.x, 1.0f);
    na.y = -fminf(a2.y, 1.0f);
    ri.x = 1.0f / fmaxf(r2.x, 1.0f);
    ri.y = 1.0f / fmaxf(r2.y, 1.0f);
    bool sq = (ri.x == 0.5f) && (ri.y == 0.5f);
    // term3 via the SAME approx path as term2 so the x->0 limit cancels exactly
    t3.x = sq ? f_sqt(d2.x) : f_ex2(ri.x * f_lg2(d2.x));
    t3.y = sq ? f_sqt(d2.y) : f_ex2(ri.y * f_lg2(d2.y));

    int t0     = chunk * CHUNK;
    int tstart = t0 - HALO; if (tstart < 0) tstart = 0;
    int tend   = t0 + CHUNK;

    const float2* px = (const float2*)(x   + ((size_t)b * Tn + tstart) * Cn + c);
    float2*       po = (float2*)      (out + ((size_t)b * Tn + t0)     * Cn + c);

    if (sq) run_seq<true >(px, po, tstart, t0, tend, na, d2, ri, t3);
    else    run_seq<false>(px, po, tstart, t0, tend, na, d2, ri, t3);
}

extern "C" void kernel_launch(void* const* d_in, const int* in_sizes, int n_in,
                              void* d_out, int out_size) {
    const float* x     = (const float*)d_in[0];
    const float* alpha = (const float*)d_in[1];
    const float* delta = (const float*)d_in[2];
    const float* root  = (const float*)d_in[3];
    float*       out   = (float*)d_out;
    (void)in_sizes; (void)n_in; (void)out_size;

    pcen_kernel<<<NBLOCKS, THREADS>>>(x, alpha, delta, root, out);
}

// round 5
// speedup vs baseline: 1.7329x; 1.3886x over previous
#include <cuda_runtime.h>
#include <cstddef>

// PCEN: out = (x / (FLOOR + ema(x))^alpha + delta)^(1/root) - delta^(1/root)
// ema: m_t = s*x_t + (1-s)*m_{t-1}, m_0 = x_0, s = 0.025.
//
// R5: identical to R4 except __launch_bounds__(THREADS, 1): the min-blocks=1
// hint gives ptxas a 255-reg budget so the 16-row float2 tile stays register
// resident (R2 shape, regs=88) and the 16 LDG.64s issue back-to-back (MLP=16).
// NC=16 chunks (CHUNK=256, HALO=257), 2048 warps, halo re-reads hit L2,
// streaming stores.

namespace {
constexpr int   Bn = 64, Tn = 4096, Cn = 128;
constexpr float S_COEF = 0.025f;
constexpr float INV_S  = 40.0f;
constexpr float OMS    = 0.975f;
constexpr float FLOORV = 1e-6f;
constexpr int   NC     = 16;              // chunks along T
constexpr int   CHUNK  = Tn / NC;         // 256
constexpr int   HALO   = 257;             // 256 burn-in updates -> decay 1.5e-3
constexpr int   U      = 16;              // rows per tile (MLP)
constexpr int   THREADS = 128;            // 4 warps/block
constexpr int   NWARPS  = Bn * NC * 2;    // 2048 float2-warps
constexpr int   NBLOCKS = NWARPS * 32 / THREADS;  // 512
constexpr int   STRIDE  = Cn / 2;         // float2 elems per T-row
}

__device__ __forceinline__ float f_lg2(float x) {
    float r; asm("lg2.approx.f32 %0, %1;" : "=f"(r) : "f"(x)); return r;
}
__device__ __forceinline__ float f_ex2(float x) {
    float r; asm("ex2.approx.f32 %0, %1;" : "=f"(r) : "f"(x)); return r;
}
__device__ __forceinline__ float f_sqt(float x) {
    float r; asm("sqrt.approx.f32 %0, %1;" : "=f"(r) : "f"(x)); return r;
}

// Pointwise PCEN. mp = m/S (scaled EMA state). SQ = (1/root == 0.5) fast path.
template <bool SQ>
__device__ __forceinline__ float pcen_pt(float xv, float mp, float na, float d,
                                         float ri, float t3) {
    float mm     = fmaf(S_COEF, mp, FLOORV);       // FLOOR + m (off the chain)
    float inv_t1 = f_ex2(na * f_lg2(mm));          // (FLOOR+m)^(-alpha)
    float y      = fmaf(xv, inv_t1, d);            // x/term1 + delta
    float t2     = SQ ? f_sqt(y) : f_ex2(ri * f_lg2(y));
    return t2 - t3;
}

template <bool SQ>
__device__ __forceinline__ void run_seq(const float2* __restrict__ px,
                                        float2* __restrict__ po,
                                        int tstart, int t0, int tend,
                                        float2 na, float2 d, float2 ri, float2 t3) {
    float2 x0 = px[0];
    float mx = x0.x * INV_S;            // scaled state m' = m/S; m_init = x_init
    float my = x0.y * INV_S;
    const float2* p = px + STRIDE;

    if (tstart == t0) {                 // chunk 0 emits row 0 (m = x_0, exact)
        float2 o;
        o.x = pcen_pt<SQ>(x0.x, mx, na.x, d.x, ri.x, t3.x);
        o.y = pcen_pt<SQ>(x0.y, my, na.y, d.y, ri.y, t3.y);
        __stcs(po, o);
        po += STRIDE;
    }

    // ---- halo burn-in: EMA update only, batched loads ----
    int nh = t0 - (tstart + 1);         // 256 for chunks > 0, -1 for chunk 0
    int hb = nh / U;                    // 16 full tiles (nh divisible by U)
    for (int g = 0; g < hb; ++g) {
        float2 xs[U];
        #pragma unroll
        for (int i = 0; i < U; ++i) xs[i] = p[i * STRIDE];
        #pragma unroll
        for (int i = 0; i < U; ++i) {
            mx = fmaf(OMS, mx, xs[i].x);
            my = fmaf(OMS, my, xs[i].y);
        }
        p += U * STRIDE;
    }
    int hr = nh - hb * U;               // 0 for chunks > 0
    for (int i = 0; i < hr; ++i) {
        float2 xv = p[i * STRIDE];
        mx = fmaf(OMS, mx, xv.x);
        my = fmaf(OMS, my, xv.y);
    }
    if (hr > 0) p += hr * STRIDE;

    // ---- emit region ----
    int ne = (tstart == t0) ? (tend - t0 - 1) : (tend - t0);
    int mt = ne / U;
    int rem = ne - mt * U;

    for (int it = 0; it < mt; ++it) {
        float2 xs[U], os[U];
        #pragma unroll
        for (int i = 0; i < U; ++i) xs[i] = p[i * STRIDE];   // batched LDG.64 x16
        #pragma unroll
        for (int i = 0; i < U; ++i) {
            mx = fmaf(OMS, mx, xs[i].x);                     // 4-cyc chain
            my = fmaf(OMS, my, xs[i].y);
            os[i].x = pcen_pt<SQ>(xs[i].x, mx, na.x, d.x, ri.x, t3.x);
            os[i].y = pcen_pt<SQ>(xs[i].y, my, na.y, d.y, ri.y, t3.y);
        }
        #pragma unroll
        for (int i = 0; i < U; ++i) __stcs(po + i * STRIDE, os[i]);
        p  += U * STRIDE;
        po += U * STRIDE;
    }
    for (int i = 0; i < rem; ++i) {
        float2 xv = p[i * STRIDE];
        mx = fmaf(OMS, mx, xv.x);
        my = fmaf(OMS, my, xv.y);
        float2 o;
        o.x = pcen_pt<SQ>(xv.x, mx, na.x, d.x, ri.x, t3.x);
        o.y = pcen_pt<SQ>(xv.y, my, na.y, d.y, ri.y, t3.y);
        __stcs(po + i * STRIDE, o);
    }
}

__global__ void __launch_bounds__(THREADS, 1)
pcen_kernel(const float* __restrict__ x,
            const float* __restrict__ alpha,
            const float* __restrict__ delta,
            const float* __restrict__ root,
            float* __restrict__ out) {
    int gtid = blockIdx.x * blockDim.x + threadIdx.x;
    int w    = gtid >> 5;
    int lane = threadIdx.x & 31;

    // warp -> (b, chunk, half); 32 warps per batch; thread -> 2 channels
    int b     = w >> 5;
    int r     = w & 31;
    int chunk = r >> 1;
    int half  = r & 1;
    int c     = half * 64 + lane * 2;

    // per-channel constants (x2)
    float2 a2 = *(const float2*)(alpha + c);
    float2 d2 = *(const float2*)(delta + c);
    float2 r2 = *(const float2*)(root  + c);

    float2 na, ri, t3;
    na.x = -fminf(a2.x, 1.0f);
    na.y = -fminf(a2.y, 1.0f);
    ri.x = 1.0f / fmaxf(r2.x, 1.0f);
    ri.y = 1.0f / fmaxf(r2.y, 1.0f);
    bool sq = (ri.x == 0.5f) && (ri.y == 0.5f);
    // term3 via the SAME approx path as term2 so the x->0 limit cancels exactly
    t3.x = sq ? f_sqt(d2.x) : f_ex2(ri.x * f_lg2(d2.x));
    t3.y = sq ? f_sqt(d2.y) : f_ex2(ri.y * f_lg2(d2.y));

    int t0     = chunk * CHUNK;
    int tstart = t0 - HALO; if (tstart < 0) tstart = 0;
    int tend   = t0 + CHUNK;

    const float2* px = (const float2*)(x   + ((size_t)b * Tn + tstart) * Cn + c);
    float2*       po = (float2*)      (out + ((size_t)b * Tn + t0)     * Cn + c);

    if (sq) run_seq<true >(px, po, tstart, t0, tend, na, d2, ri, t3);
    else    run_seq<false>(px, po, tstart, t0, tend, na, d2, ri, t3);
}

extern "C" void kernel_launch(void* const* d_in, const int* in_sizes, int n_in,
                              void* d_out, int out_size) {
    const float* x     = (const float*)d_in[0];
    const float* alpha = (const float*)d_in[1];
    const float* delta = (const float*)d_in[2];
    const float* root  = (const float*)d_in[3];
    float*       out   = (float*)d_out;
    (void)in_sizes; (void)n_in; (void)out_size;

    pcen_kernel<<<NBLOCKS, THREADS>>>(x, alpha, delta, root, out);
}

// round 6
// speedup vs baseline: 1.8851x; 1.0878x over previous
#include <cuda_runtime.h>
#include <cstddef>

// PCEN: out = (x / (FLOOR + ema(x))^alpha + delta)^(1/root) - delta^(1/root)
// ema: m_t = s*x_t + (1-s)*m_{t-1}, m_0 = x_0, s = 0.025.
//
// R6: software-pipelined tile walk with a STATIC double buffer (two named
// register arrays, even/odd unrolled loop -> no dynamic indexing -> no spill).
// Each warp always has the next 16 LDG.64s in flight while computing the
// current tile. Unified halo/emit walk: state init m' = 40*x[tstart] makes
// row 0 of chunk 0 go through the normal emit path (no remainder code).
// NC=16 (CHUNK=256, 256 halo updates), 2048 warps, streaming stores.

namespace {
constexpr int   Bn = 64, Tn = 4096, Cn = 128;
constexpr float S_COEF = 0.025f;
constexpr float INV_S  = 40.0f;           // 1/s
constexpr float OMS    = 0.975f;
constexpr float FLOORV = 1e-6f;
constexpr int   NC     = 16;              // chunks along T
constexpr int   CHUNK  = Tn / NC;         // 256
constexpr int   HALO   = 256;             // burn-in rows (decay 0.975^256~1.5e-3)
constexpr int   U      = 16;              // rows per tile
constexpr int   THREADS = 128;            // 4 warps/block
constexpr int   NWARPS  = Bn * NC * 2;    // 2048 float2-warps
constexpr int   NBLOCKS = NWARPS * 32 / THREADS;  // 512
constexpr int   STRIDE  = Cn / 2;         // float2 elems per T-row
}

__device__ __forceinline__ float f_lg2(float x) {
    float r; asm("lg2.approx.f32 %0, %1;" : "=f"(r) : "f"(x)); return r;
}
__device__ __forceinline__ float f_ex2(float x) {
    float r; asm("ex2.approx.f32 %0, %1;" : "=f"(r) : "f"(x)); return r;
}
__device__ __forceinline__ float f_sqt(float x) {
    float r; asm("sqrt.approx.f32 %0, %1;" : "=f"(r) : "f"(x)); return r;
}

// Pointwise PCEN. mp = m/S (scaled EMA state). SQ = (1/root == 0.5) fast path.
template <bool SQ>
__device__ __forceinline__ float pcen_pt(float xv, float mp, float na, float d,
                                         float ri, float t3) {
    float mm     = fmaf(S_COEF, mp, FLOORV);       // FLOOR + m (off the chain)
    float inv_t1 = f_ex2(na * f_lg2(mm));          // (FLOOR+m)^(-alpha)
    float y      = fmaf(xv, inv_t1, d);            // x/term1 + delta
    float t2     = SQ ? f_sqt(y) : f_ex2(ri * f_lg2(y));
    return t2 - t3;
}

// Consume one U-row tile held in registers. emit is warp-uniform.
template <bool SQ>
__device__ __forceinline__ void consume_tile(const float2* __restrict__ xs,
                                             bool emit, float2* __restrict__ po,
                                             int emit_off,
                                             float& mx, float& my,
                                             float2 na, float2 d, float2 ri,
                                             float2 t3) {
    if (emit) {
        float2* pot = po + (size_t)emit_off * STRIDE;
        #pragma unroll
        for (int i = 0; i < U; ++i) {
            mx = fmaf(OMS, mx, xs[i].x);           // 4-cyc dependent chain
            my = fmaf(OMS, my, xs[i].y);
            float2 o;
            o.x = pcen_pt<SQ>(xs[i].x, mx, na.x, d.x, ri.x, t3.x);
            o.y = pcen_pt<SQ>(xs[i].y, my, na.y, d.y, ri.y, t3.y);
            __stcs(pot + i * STRIDE, o);
        }
    } else {
        #pragma unroll
        for (int i = 0; i < U; ++i) {
            mx = fmaf(OMS, mx, xs[i].x);
            my = fmaf(OMS, my, xs[i].y);
        }
    }
}

template <bool SQ>
__device__ __forceinline__ void run_seq(const float2* __restrict__ p,
                                        float2* __restrict__ po,
                                        int NH, int NT,
                                        float2 na, float2 d, float2 ri, float2 t3) {
    // scaled EMA state m' = m/S. Init so that after consuming row 0 of tile 0,
    // m = x[tstart]:  m'_init = 40*x0  =>  0.975*40*x0 + x0 = 40*x0. For
    // chunk 0 this makes row 0 EXACT (m_0 = x_0) through the normal path.
    float2 x0 = p[0];
    float mx = INV_S * x0.x;
    float my = INV_S * x0.y;

    float2 bufA[U], bufB[U];
    #pragma unroll
    for (int i = 0; i < U; ++i) bufA[i] = p[i * STRIDE];    // preload tile 0

    // NT is even (16 or 32): tile t+1 always exists inside the loop.
    for (int t = 0; t < NT; t += 2) {
        const float2* p1 = p + (size_t)(t + 1) * U * STRIDE;
        #pragma unroll
        for (int i = 0; i < U; ++i) bufB[i] = p1[i * STRIDE];   // prefetch t+1

        consume_tile<SQ>(bufA, t >= NH, po, (t - NH) * U, mx, my, na, d, ri, t3);

        if (t + 2 < NT) {
            const float2* p2 = p + (size_t)(t + 2) * U * STRIDE;
            #pragma unroll
            for (int i = 0; i < U; ++i) bufA[i] = p2[i * STRIDE];  // prefetch t+2
        }

        consume_tile<SQ>(bufB, t + 1 >= NH, po, (t + 1 - NH) * U, mx, my, na, d, ri, t3);
    }
}

__global__ void __launch_bounds__(THREADS, 1)
pcen_kernel(const float* __restrict__ x,
            const float* __restrict__ alpha,
            const float* __restrict__ delta,
            const float* __restrict__ root,
            float* __restrict__ out) {
    int gtid = blockIdx.x * blockDim.x + threadIdx.x;
    int w    = gtid >> 5;
    int lane = threadIdx.x & 31;

    // warp -> (b, chunk, half); 32 warps per batch; thread -> 2 channels
    int b     = w >> 5;
    int r     = w & 31;
    int chunk = r >> 1;
    int half  = r & 1;
    int c     = half * 64 + lane * 2;

    // per-channel constants (x2)
    float2 a2 = *(const float2*)(alpha + c);
    float2 d2 = *(const float2*)(delta + c);
    float2 r2 = *(const float2*)(root  + c);

    float2 na, ri, t3;
    na.x = -fminf(a2.x, 1.0f);
    na.y = -fminf(a2.y, 1.0f);
    ri.x = 1.0f / fmaxf(r2.x, 1.0f);
    ri.y = 1.0f / fmaxf(r2.y, 1.0f);
    bool sq = (ri.x == 0.5f) && (ri.y == 0.5f);
    // term3 via the SAME approx path as term2 so the x->0 limit cancels exactly
    t3.x = sq ? f_sqt(d2.x) : f_ex2(ri.x * f_lg2(d2.x));
    t3.y = sq ? f_sqt(d2.y) : f_ex2(ri.y * f_lg2(d2.y));

    int t0     = chunk * CHUNK;
    int tstart = (chunk == 0) ? 0 : (t0 - HALO);
    int NH     = (t0 - tstart) / U;          // 0 (chunk 0) or 16
    int NT     = NH + CHUNK / U;             // 16 or 32 (always even)

    const float2* px = (const float2*)(x   + ((size_t)b * Tn + tstart) * Cn + c);
    float2*       po = (float2*)      (out + ((size_t)b * Tn + t0)     * Cn + c);

    if (sq) run_seq<true >(px, po, NH, NT, na, d2, ri, t3);
    else    run_seq<false>(px, po, NH, NT, na, d2, ri, t3);
}

extern "C" void kernel_launch(void* const* d_in, const int* in_sizes, int n_in,
                              void* d_out, int out_size) {
    const float* x     = (const float*)d_in[0];
    const float* alpha = (const float*)d_in[1];
    const float* delta = (const float*)d_in[2];
    const float* root  = (const float*)d_in[3];
    float*       out   = (float*)d_out;
    (void)in_sizes; (void)n_in; (void)out_size;

    pcen_kernel<<<NBLOCKS, THREADS>>>(x, alpha, delta, root, out);
}